// round 10
// baseline (speedup 1.0000x reference)
#include <cuda_runtime.h>
#include <cuda_fp16.h>
#include <stdint.h>

#define MTOT  131072
#define KDIM  512
#define NQKV  1536
#define HEADS 16
#define DH    32
#define WIN   64
#define NB    2048

// ---------------- scratch (device globals; allocation-free) ----------------
__device__ __half g_xh[(size_t)MTOT * KDIM];        // x in fp16           128MB
__device__ __half g_wqkv_t[(size_t)NQKV * KDIM];    // w_qkv^T fp16        1.5MB
__device__ __half g_wproj_t[(size_t)KDIM * KDIM];   // w_proj^T fp16       0.5MB
__device__ __half g_qkv[(size_t)NB * HEADS * 3 * WIN * DH];  // q,k,v      384MB
__device__ __half g_attnout[(size_t)MTOT * KDIM];   // attention output    128MB

// ---------------- PTX helpers (arch-portable) ----------------
__device__ __forceinline__ uint32_t smem_u32(const void* p) {
    uint32_t a;
    asm("{ .reg .u64 t; cvta.to.shared.u64 t, %1; cvt.u32.u64 %0, t; }" : "=r"(a) : "l"(p));
    return a;
}
__device__ __forceinline__ void cpasync16(uint32_t s, const void* g) {
    asm volatile("cp.async.cg.shared.global [%0], [%1], 16;\n" :: "r"(s), "l"(g));
}
__device__ __forceinline__ void ldsm_x4(uint32_t* r, const void* p) {
    uint32_t a = smem_u32(p);
    asm volatile("ldmatrix.sync.aligned.m8n8.x4.shared.b16 {%0,%1,%2,%3}, [%4];"
                 : "=r"(r[0]), "=r"(r[1]), "=r"(r[2]), "=r"(r[3]) : "r"(a));
}
__device__ __forceinline__ void ldsm_x4_t(uint32_t* r, const void* p) {
    uint32_t a = smem_u32(p);
    asm volatile("ldmatrix.sync.aligned.m8n8.x4.trans.shared.b16 {%0,%1,%2,%3}, [%4];"
                 : "=r"(r[0]), "=r"(r[1]), "=r"(r[2]), "=r"(r[3]) : "r"(a));
}
__device__ __forceinline__ void mma16816(float* c, const uint32_t* a, uint32_t b0, uint32_t b1) {
    asm volatile(
        "mma.sync.aligned.m16n8k16.row.col.f32.f16.f16.f32 "
        "{%0,%1,%2,%3},{%4,%5,%6,%7},{%8,%9},{%0,%1,%2,%3};"
        : "+f"(c[0]), "+f"(c[1]), "+f"(c[2]), "+f"(c[3])
        : "r"(a[0]), "r"(a[1]), "r"(a[2]), "r"(a[3]), "r"(b0), "r"(b1));
}
__device__ __forceinline__ uint32_t packh2(float a, float b) {
    __half2 h = __floats2half2_rn(a, b);
    return *(uint32_t*)&h;
}

#define HAS_TCGEN05 (defined(__CUDA_ARCH_FEAT_SM103_ALL) || defined(__CUDA_ARCH_FEAT_SM100_ALL) || defined(__CUDA_ARCH_FEAT_SM101_ALL))

#if HAS_TCGEN05
__device__ __forceinline__ uint32_t elect_one() {
    uint32_t p;
    asm volatile("{\n\t.reg .pred p;\n\telect.sync _|p, 0xFFFFFFFF;\n\tselp.b32 %0, 1, 0, p;\n\t}" : "=r"(p));
    return p;
}
// SW128 smem descriptor: layout=2 (SW128), version=1, SBO=64, LBO=1
#define SMEM_DESC_BASE \
    ((uint64_t(2) << 61) | (uint64_t(1) << 46) | (uint64_t(64) << 32) | (uint64_t(1) << 16))
#define MAKE_DESC(addr) (SMEM_DESC_BASE | (((uint64_t)((addr) >> 4)) & 0x3FFF))

#define MBARRIER_INIT(a, n) \
    asm volatile("mbarrier.init.shared.b64 [%0], %1;" :: "r"((uint32_t)(a)), "r"((uint32_t)(n)) : "memory")
#define MBARRIER_INVAL(a) \
    asm volatile("mbarrier.inval.shared.b64 [%0];" :: "r"((uint32_t)(a)) : "memory")
#define MBARRIER_WAIT_PARITY(mbar_smem_addr, phase_parity) do { \
    uint32_t _mbar = (uint32_t)(mbar_smem_addr); \
    uint32_t _parity = (uint32_t)(phase_parity); \
    uint32_t _done; \
    asm volatile( \
        "{\n\t.reg .pred p;\n\t" \
        "mbarrier.try_wait.parity.acquire.cta.shared::cta.b64 p, [%1], %2;\n\t" \
        "selp.b32 %0, 1, 0, p;\n\t}" \
        : "=r"(_done) : "r"(_mbar), "r"(_parity) : "memory"); \
    if (!_done) { \
        asm volatile( \
            "{\n\t.reg .pred P1;\n\t" \
            "WAIT_LOOP_%=:\n\t" \
            "mbarrier.try_wait.parity.acquire.cta.shared::cta.b64 P1, [%0], %1, 0x989680;\n\t" \
            "@P1 bra.uni WAIT_DONE_%=;\n\t" \
            "bra.uni WAIT_LOOP_%=;\n\t" \
            "WAIT_DONE_%=:\n\t}" \
            :: "r"(_mbar), "r"(_parity) : "memory"); \
    } \
} while(0)

#define TCGEN05_ALLOC(sa, n) \
    asm volatile("tcgen05.alloc.cta_group::1.sync.aligned.shared::cta.b32 [%0], %1;" \
                 :: "r"((uint32_t)(sa)), "r"((uint32_t)(n)) : "memory")
#define TCGEN05_DEALLOC(t, n) \
    asm volatile("tcgen05.dealloc.cta_group::1.sync.aligned.b32 %0, %1;" :: "r"(t), "r"((uint32_t)(n)))
#define TCGEN05_RELINQ() \
    asm volatile("tcgen05.relinquish_alloc_permit.cta_group::1.sync.aligned;")
#define TCGEN05_COMMIT(a) \
    asm volatile("tcgen05.commit.cta_group::1.mbarrier::arrive::one.shared::cluster.b64 [%0];" \
                 :: "r"((uint32_t)(a)) : "memory")
#define TCGEN05_WAIT_LD()  asm volatile("tcgen05.wait::ld.sync.aligned;" ::: "memory")
#define TCGEN05_FENCE_BEFORE() asm volatile("tcgen05.fence::before_thread_sync;" ::: "memory")
#define TCGEN05_FENCE_AFTER()  asm volatile("tcgen05.fence::after_thread_sync;" ::: "memory")
#define FENCE_PROXY_ASYNC() asm volatile("fence.proxy.async.shared::cta;" ::: "memory")

__device__ __forceinline__ void tc_mma_f16_ss(uint32_t d_tmem, uint64_t a_desc, uint64_t b_desc,
                                              uint32_t idesc, uint32_t en) {
    asm volatile(
        "{\n\t.reg .pred p;\n\tsetp.ne.u32 p, %4, 0;\n\t"
        "tcgen05.mma.cta_group::1.kind::f16 [%0], %1, %2, %3, {%5,%5,%5,%5}, p;\n\t}"
        :: "r"(d_tmem), "l"(a_desc), "l"(b_desc), "r"(idesc), "r"(en), "r"(0u)
        : "memory");
}

#define LDTM_X32(r, addr) \
    asm volatile( \
        "tcgen05.ld.sync.aligned.32x32b.x32.b32 " \
        "{%0, %1, %2, %3, %4, %5, %6, %7, " \
        " %8, %9, %10, %11, %12, %13, %14, %15, " \
        " %16, %17, %18, %19, %20, %21, %22, %23, " \
        " %24, %25, %26, %27, %28, %29, %30, %31}, [%32];" \
        : "=r"((r)[0]),  "=r"((r)[1]),  "=r"((r)[2]),  "=r"((r)[3]), \
          "=r"((r)[4]),  "=r"((r)[5]),  "=r"((r)[6]),  "=r"((r)[7]), \
          "=r"((r)[8]),  "=r"((r)[9]),  "=r"((r)[10]), "=r"((r)[11]), \
          "=r"((r)[12]), "=r"((r)[13]), "=r"((r)[14]), "=r"((r)[15]), \
          "=r"((r)[16]), "=r"((r)[17]), "=r"((r)[18]), "=r"((r)[19]), \
          "=r"((r)[20]), "=r"((r)[21]), "=r"((r)[22]), "=r"((r)[23]), \
          "=r"((r)[24]), "=r"((r)[25]), "=r"((r)[26]), "=r"((r)[27]), \
          "=r"((r)[28]), "=r"((r)[29]), "=r"((r)[30]), "=r"((r)[31]) \
        : "r"(addr))
#endif  // HAS_TCGEN05

// ---------------- converters ----------------
__global__ void conv_x_kernel(const float* __restrict__ x) {
    size_t i = (size_t)blockIdx.x * blockDim.x + threadIdx.x;
    float4 v = *(const float4*)(x + i * 4);
    __half2 a = __floats2half2_rn(v.x, v.y);
    __half2 b = __floats2half2_rn(v.z, v.w);
    uint2 o;
    o.x = *(uint32_t*)&a;
    o.y = *(uint32_t*)&b;
    *(uint2*)(g_xh + i * 4) = o;
}

__global__ void conv_w_kernel(const float* __restrict__ wqkv, const float* __restrict__ wproj) {
    int i = blockIdx.x * blockDim.x + threadIdx.x;
    if (i < NQKV * KDIM) {
        int n = i >> 9, k = i & 511;
        g_wqkv_t[i] = __float2half_rn(wqkv[(size_t)k * NQKV + n]);
    }
    if (i < KDIM * KDIM) {
        int n = i >> 9, k = i & 511;
        g_wproj_t[i] = __float2half_rn(wproj[(size_t)k * KDIM + n]);
    }
}

// ---------------- GEMM: C tile[128x128] = A[128x512] x Bt[128x512]^T ----------------
// grid: (Ntiles, Mtiles), blockIdx.x = bn (fastest -> L2 A-panel reuse), 256 threads.
// Two device paths: tcgen05 (sm_103a cubin) / legacy mma.sync (compute_103 PTX).
#define GEMM_SMEM_BYTES 99872   // max of both paths, incl. 1KB alignment slack

template <int MODE>   // 0 = qkv epilogue, 1 = proj epilogue
__global__ __launch_bounds__(256)
void gemm_tc_kernel(const float* __restrict__ bias, float* __restrict__ outf) {
    extern __shared__ char smem_raw[];
    const int bn = blockIdx.x, bm = blockIdx.y;
    const int tid = threadIdx.x, lane = tid & 31, warp = tid >> 5;

    const __half* A  = (MODE == 0) ? g_xh     : g_attnout;
    const __half* Bt = (MODE == 0) ? g_wqkv_t : g_wproj_t;
    const __half* gA = A  + (size_t)bm * 128 * KDIM;
    const __half* gB = Bt + (size_t)bn * 128 * KDIM;
    const float qscale = 0.17677669529663687f;   // 1/sqrt(32)

#if HAS_TCGEN05
    // ================= tcgen05 path =================
    const uint32_t smb = (smem_u32(smem_raw) + 1023u) & ~1023u;   // 1KB-align for SW128 desc
    const uint32_t BIAS_OFF = 98304, STM_OFF = 98816, MB_OFF = 98824;

    if (tid == 0) {
        MBARRIER_INIT(smb + MB_OFF + 0, 1);
        MBARRIER_INIT(smb + MB_OFF + 8, 1);
        MBARRIER_INIT(smb + MB_OFF + 16, 1);
    }
    if (warp == 0) {
        TCGEN05_ALLOC(smb + STM_OFF, 128);
        TCGEN05_RELINQ();
    }
    if (tid < 128) {
        float b = bias[bn * 128 + tid];
        asm volatile("st.shared.f32 [%0], %1;" :: "r"(smb + BIAS_OFF + tid * 4), "f"(b));
    }
    __syncthreads();
    uint32_t tmem;
    asm volatile("ld.shared.b32 %0, [%1];" : "=r"(tmem) : "r"(smb + STM_OFF));

    // stage buffer: A 16KB + B 16KB, 3 stages
    auto load_tile = [&](int t, int buf) {
        const __half* gAk = gA + t * 64;
        const __half* gBk = gB + t * 64;
        const uint32_t base = smb + buf * 32768;
        #pragma unroll
        for (int c = 0; c < 8; ++c) {
            int idx = tid + c * 256;                 // 0..2047
            int isB = idx >> 10;
            int e = idx & 1023;
            int row = e >> 3, c16 = e & 7;
            uint32_t off = row * 128 + c16 * 16;
            uint32_t sw = off ^ ((off >> 3) & 0x70);
            const __half* src = (isB ? gBk : gAk) + (size_t)row * KDIM + c16 * 8;
            cpasync16(base + isB * 16384 + sw, src);
        }
        asm volatile("cp.async.commit_group;\n" ::: "memory");
    };

    load_tile(0, 0);
    load_tile(1, 1);
    load_tile(2, 2);

    const uint32_t idesc = (1u << 4) | ((128u / 8) << 17) | ((128u / 16) << 24);
    int par[3] = {0, 0, 0};
    #pragma unroll
    for (int kt = 0; kt < 8; ++kt) {
        const int buf = kt % 3;
        const int pend = (7 - kt) > 2 ? 2 : (7 - kt);
        if (pend == 2)      asm volatile("cp.async.wait_group 2;\n" ::: "memory");
        else if (pend == 1) asm volatile("cp.async.wait_group 1;\n" ::: "memory");
        else                asm volatile("cp.async.wait_group 0;\n" ::: "memory");
        FENCE_PROXY_ASYNC();
        __syncthreads();

        if (warp == 0 && elect_one()) {
            uint64_t ad = MAKE_DESC(smb + buf * 32768);
            uint64_t bd = MAKE_DESC(smb + buf * 32768 + 16384);
            #pragma unroll
            for (int s = 0; s < 4; ++s)
                tc_mma_f16_ss(tmem, ad + s * 2, bd + s * 2, idesc, (kt > 0 || s > 0) ? 1u : 0u);
            TCGEN05_COMMIT(smb + MB_OFF + buf * 8);
        }

        if (kt + 3 < 8) {
            MBARRIER_WAIT_PARITY(smb + MB_OFF + buf * 8, par[buf]);
            par[buf] ^= 1;
            load_tile(kt + 3, buf);
        }
    }
    MBARRIER_WAIT_PARITY(smb + MB_OFF + 8, par[1]);
    TCGEN05_FENCE_AFTER();

    // epilogue: D = 128 lanes x 128 cols fp32.
    {
        const int sub = warp & 3;
        const int row = bm * 128 + sub * 32 + lane;
        const uint32_t taddr = tmem + ((uint32_t)sub << 21);
        #pragma unroll
        for (int chunk = 0; chunk < 2; ++chunk) {
            const int c0 = (warp >> 2) * 64 + chunk * 32;
            uint32_t regs[32];
            LDTM_X32(regs, taddr + c0);
            TCGEN05_WAIT_LD();
            float sb[32];
            #pragma unroll
            for (int j = 0; j < 32; ++j)
                asm volatile("ld.shared.f32 %0, [%1];" : "=f"(sb[j]) : "r"(smb + BIAS_OFF + (c0 + j) * 4));

            if (MODE == 0) {
                const int cg0 = bn * 128 + c0;
                const int three = cg0 >> 9, head = (cg0 >> 5) & 15;
                const float sc = (three == 0) ? qscale : 1.0f;
                const int b_idx = row >> 6, rw = row & 63;
                __half2* dst = (__half2*)(g_qkv +
                    ((((size_t)b_idx * HEADS + head) * 3 + three) * WIN + rw) * DH);
                #pragma unroll
                for (int j = 0; j < 16; ++j) {
                    float v0 = (__uint_as_float(regs[2 * j])     + sb[2 * j])     * sc;
                    float v1 = (__uint_as_float(regs[2 * j + 1]) + sb[2 * j + 1]) * sc;
                    dst[j] = __floats2half2_rn(v0, v1);
                }
            } else {
                float* dst = outf + (size_t)row * KDIM + bn * 128 + c0;
                #pragma unroll
                for (int j = 0; j < 8; ++j) {
                    float4 v;
                    v.x = __uint_as_float(regs[4 * j])     + sb[4 * j];
                    v.y = __uint_as_float(regs[4 * j + 1]) + sb[4 * j + 1];
                    v.z = __uint_as_float(regs[4 * j + 2]) + sb[4 * j + 2];
                    v.w = __uint_as_float(regs[4 * j + 3]) + sb[4 * j + 3];
                    *(float4*)(dst + 4 * j) = v;
                }
            }
        }
    }
    TCGEN05_FENCE_BEFORE();
    __syncthreads();
    if (tid == 0) {
        MBARRIER_INVAL(smb + MB_OFF + 0);
        MBARRIER_INVAL(smb + MB_OFF + 8);
        MBARRIER_INVAL(smb + MB_OFF + 16);
    }
    __syncthreads();
    if (warp == 0) TCGEN05_DEALLOC(tmem, 128);

#else
    // ================= legacy mma.sync path =================
    __half* sA = (__half*)smem_raw;               // [2][128*40]
    __half* sB = sA + 2 * 128 * 40;               // [2][128*40]
    const int wm = warp >> 2, wn = warp & 3;

    float acc[4][4][4];
    #pragma unroll
    for (int i = 0; i < 4; ++i)
        #pragma unroll
        for (int j = 0; j < 4; ++j)
            #pragma unroll
            for (int e = 0; e < 4; ++e) acc[i][j][e] = 0.f;

    auto load_tile = [&](int kt, int buf) {
        __half* dA = sA + buf * 128 * 40;
        __half* dB = sB + buf * 128 * 40;
        #pragma unroll
        for (int c = tid; c < 512; c += 256) {
            int row = c >> 2, cc = c & 3;
            cpasync16(smem_u32(dA + row * 40 + cc * 8), gA + (size_t)row * KDIM + kt * 32 + cc * 8);
            cpasync16(smem_u32(dB + row * 40 + cc * 8), gB + (size_t)row * KDIM + kt * 32 + cc * 8);
        }
        asm volatile("cp.async.commit_group;\n" ::: "memory");
    };

    load_tile(0, 0);
    for (int kt = 0; kt < 16; ++kt) {
        const int buf = kt & 1;
        if (kt + 1 < 16) {
            load_tile(kt + 1, buf ^ 1);
            asm volatile("cp.async.wait_group 1;\n" ::: "memory");
        } else {
            asm volatile("cp.async.wait_group 0;\n" ::: "memory");
        }
        __syncthreads();

        const __half* cA = sA + buf * 128 * 40;
        const __half* cB = sB + buf * 128 * 40;
        #pragma unroll
        for (int kk = 0; kk < 2; ++kk) {
            uint32_t af[4][4];
            #pragma unroll
            for (int mi = 0; mi < 4; ++mi) {
                int row = wm * 64 + mi * 16 + (lane & 15);
                int col = kk * 16 + ((lane >> 4) << 3);
                ldsm_x4(af[mi], &cA[row * 40 + col]);
            }
            uint32_t bf[2][4];
            #pragma unroll
            for (int nh = 0; nh < 2; ++nh) {
                int row = wn * 32 + nh * 16 + (lane & 7) + ((lane & 16) ? 8 : 0);
                int col = kk * 16 + ((lane & 8) ? 8 : 0);
                ldsm_x4(bf[nh], &cB[row * 40 + col]);
            }
            #pragma unroll
            for (int mi = 0; mi < 4; ++mi)
                #pragma unroll
                for (int ni = 0; ni < 4; ++ni)
                    mma16816(acc[mi][ni], af[mi], bf[ni >> 1][(ni & 1) * 2],
                             bf[ni >> 1][(ni & 1) * 2 + 1]);
        }
        __syncthreads();
    }

    const int g = lane >> 2, t = lane & 3;
    #pragma unroll
    for (int mi = 0; mi < 4; ++mi) {
        #pragma unroll
        for (int ni = 0; ni < 4; ++ni) {
            int col = bn * 128 + wn * 32 + ni * 8 + 2 * t;
            float bc0 = bias[col], bc1 = bias[col + 1];
            #pragma unroll
            for (int hh = 0; hh < 2; ++hh) {
                int row = bm * 128 + wm * 64 + mi * 16 + g + hh * 8;
                float v0 = acc[mi][ni][hh * 2 + 0] + bc0;
                float v1 = acc[mi][ni][hh * 2 + 1] + bc1;
                if (MODE == 0) {
                    int three = col >> 9, head = (col >> 5) & 15, d = col & 31;
                    if (three == 0) { v0 *= qscale; v1 *= qscale; }
                    size_t dst = ((((size_t)(row >> 6) * HEADS + head) * 3 + three) * WIN
                                  + (row & 63)) * DH + d;
                    *(__half2*)(g_qkv + dst) = __floats2half2_rn(v0, v1);
                } else {
                    *(float2*)(outf + (size_t)row * KDIM + col) = make_float2(v0, v1);
                }
            }
        }
    }
#endif
}

// ---------------- window attention: one CTA per TWO (window, head) pairs ----------------
// 256 threads; warps 0-3 -> pair 0, warps 4-7 -> pair 1. Per-warp math identical to R2.
// Output staged in smem (dead sq region) then written as coalesced 16B float4s.
__global__ __launch_bounds__(256) void attn_kernel(const float* __restrict__ table) {
    __shared__ __half sqkv[2][3][64 * 40];
    __shared__ float stab2[2][225];

    const int pair0 = blockIdx.x * 2;
    const int tid = threadIdx.x, lane = tid & 31, warp = tid >> 5;

    // load qkv for both pairs: 1536 x 16B chunks
    const __half* base = g_qkv + (size_t)blockIdx.x * 2 * 3 * WIN * DH;
    #pragma unroll
    for (int it = 0; it < 6; ++it) {
        int c = tid + it * 256;                  // 0..1535
        int p = c / 768;
        int r = c - p * 768;
        int mat = r >> 8, rc = r & 255, row = rc >> 2, cc = rc & 3;
        float4 v = *(const float4*)(base + p * 6144 + mat * 2048 + row * 32 + cc * 8);
        *(float4*)(&sqkv[p][mat][row * 40 + cc * 8]) = v;
    }
    for (int i = tid; i < 450; i += 256) {
        int pp = i / 225, j = i - pp * 225;
        stab2[pp][j] = table[((pair0 + pp) & (HEADS - 1)) * 225 + j];
    }
    __syncthreads();

    const int pair = warp >> 2, ww = warp & 3;
    const __half* sq = sqkv[pair][0];
    const __half* sk = sqkv[pair][1];
    const __half* sv = sqkv[pair][2];
    const float* stab = stab2[pair];

    const int r0 = ww * 16;
    float s[8][4];
    #pragma unroll
    for (int i = 0; i < 8; ++i)
        #pragma unroll
        for (int e = 0; e < 4; ++e) s[i][e] = 0.f;

    // S = q k^T (q pre-scaled)
    #pragma unroll
    for (int kk = 0; kk < 2; ++kk) {
        uint32_t a[4];
        {
            int row = r0 + (lane & 15);
            int col = kk * 16 + ((lane >> 4) << 3);
            ldsm_x4(a, &sq[row * 40 + col]);
        }
        #pragma unroll
        for (int nh = 0; nh < 4; ++nh) {
            uint32_t b[4];
            int row = nh * 16 + (lane & 7) + ((lane & 16) ? 8 : 0);
            int col = kk * 16 + ((lane & 8) ? 8 : 0);
            ldsm_x4(b, &sk[row * 40 + col]);
            mma16816(s[nh * 2],     a, b[0], b[1]);
            mma16816(s[nh * 2 + 1], a, b[2], b[3]);
        }
    }

    const int g = lane >> 2, t = lane & 3;
    const int i0 = r0 + g, i1 = r0 + 8 + g;
    const int ir0 = (i0 >> 3) + 7, ic0 = (i0 & 7) + 7;
    const int ir1 = (i1 >> 3) + 7, ic1 = (i1 & 7) + 7;

    float mx0 = -1e30f, mx1 = -1e30f;
    #pragma unroll
    for (int nt = 0; nt < 8; ++nt) {
        #pragma unroll
        for (int e = 0; e < 2; ++e) {
            int m = nt * 8 + 2 * t + e;
            int dr = m >> 3, dc = m & 7;
            s[nt][e]     += stab[(ir0 - dr) * 15 + (ic0 - dc)];
            s[nt][2 + e] += stab[(ir1 - dr) * 15 + (ic1 - dc)];
            mx0 = fmaxf(mx0, s[nt][e]);
            mx1 = fmaxf(mx1, s[nt][2 + e]);
        }
    }
    mx0 = fmaxf(mx0, __shfl_xor_sync(0xffffffffu, mx0, 1));
    mx0 = fmaxf(mx0, __shfl_xor_sync(0xffffffffu, mx0, 2));
    mx1 = fmaxf(mx1, __shfl_xor_sync(0xffffffffu, mx1, 1));
    mx1 = fmaxf(mx1, __shfl_xor_sync(0xffffffffu, mx1, 2));

    float sum0 = 0.f, sum1 = 0.f;
    #pragma unroll
    for (int nt = 0; nt < 8; ++nt) {
        #pragma unroll
        for (int e = 0; e < 2; ++e) {
            s[nt][e]     = __expf(s[nt][e] - mx0);     sum0 += s[nt][e];
            s[nt][2 + e] = __expf(s[nt][2 + e] - mx1); sum1 += s[nt][2 + e];
        }
    }
    sum0 += __shfl_xor_sync(0xffffffffu, sum0, 1);
    sum0 += __shfl_xor_sync(0xffffffffu, sum0, 2);
    sum1 += __shfl_xor_sync(0xffffffffu, sum1, 1);
    sum1 += __shfl_xor_sync(0xffffffffu, sum1, 2);
    const float inv0 = 1.f / sum0, inv1 = 1.f / sum1;
    #pragma unroll
    for (int nt = 0; nt < 8; ++nt) {
        s[nt][0] *= inv0; s[nt][1] *= inv0;
        s[nt][2] *= inv1; s[nt][3] *= inv1;
    }

    // O = P v
    float o[4][4];
    #pragma unroll
    for (int i = 0; i < 4; ++i)
        #pragma unroll
        for (int e = 0; e < 4; ++e) o[i][e] = 0.f;

    #pragma unroll
    for (int kk = 0; kk < 4; ++kk) {
        uint32_t pa[4];
        pa[0] = packh2(s[2 * kk][0],     s[2 * kk][1]);
        pa[1] = packh2(s[2 * kk][2],     s[2 * kk][3]);
        pa[2] = packh2(s[2 * kk + 1][0], s[2 * kk + 1][1]);
        pa[3] = packh2(s[2 * kk + 1][2], s[2 * kk + 1][3]);
        #pragma unroll
        for (int nh = 0; nh < 2; ++nh) {
            uint32_t b[4];
            int row = kk * 16 + (lane & 7) + ((lane & 8) ? 8 : 0);
            int col = nh * 16 + ((lane & 16) ? 8 : 0);
            ldsm_x4_t(b, &sv[row * 40 + col]);
            mma16816(o[nh * 2],     pa, b[0], b[1]);
            mma16816(o[nh * 2 + 1], pa, b[2], b[3]);
        }
    }

    // stage O into the (now dead) sq region, stride 32, then coalesced write-out
    __syncthreads();
    {
        __half* so = sqkv[pair][0];
        #pragma unroll
        for (int ni = 0; ni < 4; ++ni) {
            int col = ni * 8 + 2 * t;
            *(__half2*)(so + i0 * 32 + col) = __floats2half2_rn(o[ni][0], o[ni][1]);
            *(__half2*)(so + i1 * 32 + col) = __floats2half2_rn(o[ni][2], o[ni][3]);
        }
    }
    __syncthreads();

    // copy out: 512 assignments (2 pairs x 64 rows x 4 segs of 16B)
    #pragma unroll
    for (int it = 0; it < 2; ++it) {
        int j = tid + it * 256;                  // 0..511
        int p = j >> 8, rem = j & 255;
        int r = rem >> 2, seg = rem & 3;
        int bh = pair0 + p;
        int b = bh >> 4, h = bh & (HEADS - 1);
        float4 v = *(const float4*)(&sqkv[p][0][r * 32 + seg * 8]);
        *(float4*)(g_attnout + ((size_t)b * 64 + r) * KDIM + h * 32 + seg * 8) = v;
    }
}

// ---------------- launch ----------------
extern "C" void kernel_launch(void* const* d_in, const int* in_sizes, int n_in,
                              void* d_out, int out_size) {
    const float* x     = (const float*)d_in[0];
    const float* wqkv  = (const float*)d_in[1];
    const float* bqkv  = (const float*)d_in[2];
    const float* tab   = (const float*)d_in[3];
    const float* wproj = (const float*)d_in[4];
    const float* bproj = (const float*)d_in[5];
    float* out = (float*)d_out;

    static int smem_set = 0;
    if (!smem_set) {
        cudaFuncSetAttribute(gemm_tc_kernel<0>, cudaFuncAttributeMaxDynamicSharedMemorySize, GEMM_SMEM_BYTES);
        cudaFuncSetAttribute(gemm_tc_kernel<1>, cudaFuncAttributeMaxDynamicSharedMemorySize, GEMM_SMEM_BYTES);
        smem_set = 1;
    }

    conv_x_kernel<<<65536, 256>>>(x);
    conv_w_kernel<<<3072, 256>>>(wqkv, wproj);
    gemm_tc_kernel<0><<<dim3(NQKV / 128, MTOT / 128), 256, GEMM_SMEM_BYTES>>>(bqkv, nullptr);
    attn_kernel<<<NB * HEADS / 2, 256>>>(tab);
    gemm_tc_kernel<1><<<dim3(KDIM / 128, MTOT / 128), 256, GEMM_SMEM_BYTES>>>(bproj, out);
}

// round 11
// speedup vs baseline: 1.4784x; 1.4784x over previous
#include <cuda_runtime.h>
#include <cuda_fp16.h>
#include <stdint.h>

#define MTOT  131072
#define KDIM  512
#define NQKV  1536
#define HEADS 16
#define DH    32
#define WIN   64
#define NB    2048

// ---------------- scratch (device globals; allocation-free) ----------------
__device__ __half g_xh[(size_t)MTOT * KDIM];        // x in fp16           128MB
__device__ __half g_wqkv_t[(size_t)NQKV * KDIM];    // w_qkv^T fp16        1.5MB
__device__ __half g_wproj_t[(size_t)KDIM * KDIM];   // w_proj^T fp16       0.5MB
__device__ __half g_qkv[(size_t)NB * HEADS * 3 * WIN * DH];  // q,k,v      384MB
__device__ __half g_attnout[(size_t)MTOT * KDIM];   // attention output    128MB

// ---------------- PTX helpers (arch-portable) ----------------
__device__ __forceinline__ uint32_t smem_u32(const void* p) {
    uint32_t a;
    asm("{ .reg .u64 t; cvta.to.shared.u64 t, %1; cvt.u32.u64 %0, t; }" : "=r"(a) : "l"(p));
    return a;
}
__device__ __forceinline__ void cpasync16(uint32_t s, const void* g) {
    asm volatile("cp.async.cg.shared.global [%0], [%1], 16;\n" :: "r"(s), "l"(g));
}
__device__ __forceinline__ void ldsm_x4(uint32_t* r, const void* p) {
    uint32_t a = smem_u32(p);
    asm volatile("ldmatrix.sync.aligned.m8n8.x4.shared.b16 {%0,%1,%2,%3}, [%4];"
                 : "=r"(r[0]), "=r"(r[1]), "=r"(r[2]), "=r"(r[3]) : "r"(a));
}
__device__ __forceinline__ void ldsm_x4_t(uint32_t* r, const void* p) {
    uint32_t a = smem_u32(p);
    asm volatile("ldmatrix.sync.aligned.m8n8.x4.trans.shared.b16 {%0,%1,%2,%3}, [%4];"
                 : "=r"(r[0]), "=r"(r[1]), "=r"(r[2]), "=r"(r[3]) : "r"(a));
}
__device__ __forceinline__ void mma16816(float* c, const uint32_t* a, uint32_t b0, uint32_t b1) {
    asm volatile(
        "mma.sync.aligned.m16n8k16.row.col.f32.f16.f16.f32 "
        "{%0,%1,%2,%3},{%4,%5,%6,%7},{%8,%9},{%0,%1,%2,%3};"
        : "+f"(c[0]), "+f"(c[1]), "+f"(c[2]), "+f"(c[3])
        : "r"(a[0]), "r"(a[1]), "r"(a[2]), "r"(a[3]), "r"(b0), "r"(b1));
}
__device__ __forceinline__ uint32_t packh2(float a, float b) {
    __half2 h = __floats2half2_rn(a, b);
    return *(uint32_t*)&h;
}

#define HAS_TCGEN05 (defined(__CUDA_ARCH_FEAT_SM103_ALL) || defined(__CUDA_ARCH_FEAT_SM100_ALL) || defined(__CUDA_ARCH_FEAT_SM101_ALL))

#if HAS_TCGEN05
__device__ __forceinline__ uint32_t elect_one() {
    uint32_t p;
    asm volatile("{\n\t.reg .pred p;\n\telect.sync _|p, 0xFFFFFFFF;\n\tselp.b32 %0, 1, 0, p;\n\t}" : "=r"(p));
    return p;
}
// SW128 smem descriptor: layout=2 (SW128), version=1, SBO=64, LBO=1
#define SMEM_DESC_BASE \
    ((uint64_t(2) << 61) | (uint64_t(1) << 46) | (uint64_t(64) << 32) | (uint64_t(1) << 16))
#define MAKE_DESC(addr) (SMEM_DESC_BASE | (((uint64_t)((addr) >> 4)) & 0x3FFF))

#define MBARRIER_INIT(a, n) \
    asm volatile("mbarrier.init.shared.b64 [%0], %1;" :: "r"((uint32_t)(a)), "r"((uint32_t)(n)) : "memory")
#define MBARRIER_INVAL(a) \
    asm volatile("mbarrier.inval.shared.b64 [%0];" :: "r"((uint32_t)(a)) : "memory")
#define MBARRIER_WAIT_PARITY(mbar_smem_addr, phase_parity) do { \
    uint32_t _mbar = (uint32_t)(mbar_smem_addr); \
    uint32_t _parity = (uint32_t)(phase_parity); \
    uint32_t _done; \
    asm volatile( \
        "{\n\t.reg .pred p;\n\t" \
        "mbarrier.try_wait.parity.acquire.cta.shared::cta.b64 p, [%1], %2;\n\t" \
        "selp.b32 %0, 1, 0, p;\n\t}" \
        : "=r"(_done) : "r"(_mbar), "r"(_parity) : "memory"); \
    if (!_done) { \
        asm volatile( \
            "{\n\t.reg .pred P1;\n\t" \
            "WAIT_LOOP_%=:\n\t" \
            "mbarrier.try_wait.parity.acquire.cta.shared::cta.b64 P1, [%0], %1, 0x989680;\n\t" \
            "@P1 bra.uni WAIT_DONE_%=;\n\t" \
            "bra.uni WAIT_LOOP_%=;\n\t" \
            "WAIT_DONE_%=:\n\t}" \
            :: "r"(_mbar), "r"(_parity) : "memory"); \
    } \
} while(0)

#define TCGEN05_ALLOC(sa, n) \
    asm volatile("tcgen05.alloc.cta_group::1.sync.aligned.shared::cta.b32 [%0], %1;" \
                 :: "r"((uint32_t)(sa)), "r"((uint32_t)(n)) : "memory")
#define TCGEN05_DEALLOC(t, n) \
    asm volatile("tcgen05.dealloc.cta_group::1.sync.aligned.b32 %0, %1;" :: "r"(t), "r"((uint32_t)(n)))
#define TCGEN05_RELINQ() \
    asm volatile("tcgen05.relinquish_alloc_permit.cta_group::1.sync.aligned;")
#define TCGEN05_COMMIT(a) \
    asm volatile("tcgen05.commit.cta_group::1.mbarrier::arrive::one.shared::cluster.b64 [%0];" \
                 :: "r"((uint32_t)(a)) : "memory")
#define TCGEN05_WAIT_LD()  asm volatile("tcgen05.wait::ld.sync.aligned;" ::: "memory")
#define TCGEN05_FENCE_BEFORE() asm volatile("tcgen05.fence::before_thread_sync;" ::: "memory")
#define TCGEN05_FENCE_AFTER()  asm volatile("tcgen05.fence::after_thread_sync;" ::: "memory")
#define FENCE_PROXY_ASYNC() asm volatile("fence.proxy.async.shared::cta;" ::: "memory")

__device__ __forceinline__ void tc_mma_f16_ss(uint32_t d_tmem, uint64_t a_desc, uint64_t b_desc,
                                              uint32_t idesc, uint32_t en) {
    asm volatile(
        "{\n\t.reg .pred p;\n\tsetp.ne.u32 p, %4, 0;\n\t"
        "tcgen05.mma.cta_group::1.kind::f16 [%0], %1, %2, %3, {%5,%5,%5,%5}, p;\n\t}"
        :: "r"(d_tmem), "l"(a_desc), "l"(b_desc), "r"(idesc), "r"(en), "r"(0u)
        : "memory");
}

#define LDTM_X32(r, addr) \
    asm volatile( \
        "tcgen05.ld.sync.aligned.32x32b.x32.b32 " \
        "{%0, %1, %2, %3, %4, %5, %6, %7, " \
        " %8, %9, %10, %11, %12, %13, %14, %15, " \
        " %16, %17, %18, %19, %20, %21, %22, %23, " \
        " %24, %25, %26, %27, %28, %29, %30, %31}, [%32];" \
        : "=r"((r)[0]),  "=r"((r)[1]),  "=r"((r)[2]),  "=r"((r)[3]), \
          "=r"((r)[4]),  "=r"((r)[5]),  "=r"((r)[6]),  "=r"((r)[7]), \
          "=r"((r)[8]),  "=r"((r)[9]),  "=r"((r)[10]), "=r"((r)[11]), \
          "=r"((r)[12]), "=r"((r)[13]), "=r"((r)[14]), "=r"((r)[15]), \
          "=r"((r)[16]), "=r"((r)[17]), "=r"((r)[18]), "=r"((r)[19]), \
          "=r"((r)[20]), "=r"((r)[21]), "=r"((r)[22]), "=r"((r)[23]), \
          "=r"((r)[24]), "=r"((r)[25]), "=r"((r)[26]), "=r"((r)[27]), \
          "=r"((r)[28]), "=r"((r)[29]), "=r"((r)[30]), "=r"((r)[31]) \
        : "r"(addr))
#endif  // HAS_TCGEN05

// ---------------- converters ----------------
__global__ void conv_x_kernel(const float* __restrict__ x) {
    size_t i = (size_t)blockIdx.x * blockDim.x + threadIdx.x;
    float4 v = *(const float4*)(x + i * 4);
    __half2 a = __floats2half2_rn(v.x, v.y);
    __half2 b = __floats2half2_rn(v.z, v.w);
    uint2 o;
    o.x = *(uint32_t*)&a;
    o.y = *(uint32_t*)&b;
    *(uint2*)(g_xh + i * 4) = o;
}

__global__ void conv_w_kernel(const float* __restrict__ wqkv, const float* __restrict__ wproj) {
    int i = blockIdx.x * blockDim.x + threadIdx.x;
    if (i < NQKV * KDIM) {
        int n = i >> 9, k = i & 511;
        g_wqkv_t[i] = __float2half_rn(wqkv[(size_t)k * NQKV + n]);
    }
    if (i < KDIM * KDIM) {
        int n = i >> 9, k = i & 511;
        g_wproj_t[i] = __float2half_rn(wproj[(size_t)k * KDIM + n]);
    }
}

// ---------------- GEMM: C tile[128x128] = A[128x512] x Bt[128x512]^T ----------------
// grid: (Ntiles, Mtiles), blockIdx.x = bn (fastest -> L2 A-panel reuse), 256 threads.
// Two device paths: tcgen05 (sm_103a cubin) / legacy mma.sync (compute_103 PTX).
#define GEMM_SMEM_BYTES 99872   // max of both paths, incl. 1KB alignment slack

template <int MODE>   // 0 = qkv epilogue, 1 = proj epilogue
__global__ __launch_bounds__(256)
void gemm_tc_kernel(const float* __restrict__ bias, float* __restrict__ outf) {
    extern __shared__ char smem_raw[];
    const int bn = blockIdx.x, bm = blockIdx.y;
    const int tid = threadIdx.x, lane = tid & 31, warp = tid >> 5;

    const __half* A  = (MODE == 0) ? g_xh     : g_attnout;
    const __half* Bt = (MODE == 0) ? g_wqkv_t : g_wproj_t;
    const __half* gA = A  + (size_t)bm * 128 * KDIM;
    const __half* gB = Bt + (size_t)bn * 128 * KDIM;
    const float qscale = 0.17677669529663687f;   // 1/sqrt(32)

#if HAS_TCGEN05
    // ================= tcgen05 path =================
    const uint32_t smb = (smem_u32(smem_raw) + 1023u) & ~1023u;   // 1KB-align for SW128 desc
    const uint32_t BIAS_OFF = 98304, STM_OFF = 98816, MB_OFF = 98824;

    if (tid == 0) {
        MBARRIER_INIT(smb + MB_OFF + 0, 1);
        MBARRIER_INIT(smb + MB_OFF + 8, 1);
        MBARRIER_INIT(smb + MB_OFF + 16, 1);
    }
    if (warp == 0) {
        TCGEN05_ALLOC(smb + STM_OFF, 128);
        TCGEN05_RELINQ();
    }
    if (tid < 128) {
        float b = bias[bn * 128 + tid];
        asm volatile("st.shared.f32 [%0], %1;" :: "r"(smb + BIAS_OFF + tid * 4), "f"(b));
    }
    __syncthreads();
    uint32_t tmem;
    asm volatile("ld.shared.b32 %0, [%1];" : "=r"(tmem) : "r"(smb + STM_OFF));

    // stage buffer: A 16KB + B 16KB, 3 stages
    auto load_tile = [&](int t, int buf) {
        const __half* gAk = gA + t * 64;
        const __half* gBk = gB + t * 64;
        const uint32_t base = smb + buf * 32768;
        #pragma unroll
        for (int c = 0; c < 8; ++c) {
            int idx = tid + c * 256;                 // 0..2047
            int isB = idx >> 10;
            int e = idx & 1023;
            int row = e >> 3, c16 = e & 7;
            uint32_t off = row * 128 + c16 * 16;
            uint32_t sw = off ^ ((off >> 3) & 0x70);
            const __half* src = (isB ? gBk : gAk) + (size_t)row * KDIM + c16 * 8;
            cpasync16(base + isB * 16384 + sw, src);
        }
        asm volatile("cp.async.commit_group;\n" ::: "memory");
    };

    load_tile(0, 0);
    load_tile(1, 1);
    load_tile(2, 2);

    const uint32_t idesc = (1u << 4) | ((128u / 8) << 17) | ((128u / 16) << 24);
    int par[3] = {0, 0, 0};
    #pragma unroll
    for (int kt = 0; kt < 8; ++kt) {
        const int buf = kt % 3;
        const int pend = (7 - kt) > 2 ? 2 : (7 - kt);
        if (pend == 2)      asm volatile("cp.async.wait_group 2;\n" ::: "memory");
        else if (pend == 1) asm volatile("cp.async.wait_group 1;\n" ::: "memory");
        else                asm volatile("cp.async.wait_group 0;\n" ::: "memory");
        FENCE_PROXY_ASYNC();
        __syncthreads();

        if (warp == 0 && elect_one()) {
            uint64_t ad = MAKE_DESC(smb + buf * 32768);
            uint64_t bd = MAKE_DESC(smb + buf * 32768 + 16384);
            #pragma unroll
            for (int s = 0; s < 4; ++s)
                tc_mma_f16_ss(tmem, ad + s * 2, bd + s * 2, idesc, (kt > 0 || s > 0) ? 1u : 0u);
            TCGEN05_COMMIT(smb + MB_OFF + buf * 8);
        }

        if (kt + 3 < 8) {
            MBARRIER_WAIT_PARITY(smb + MB_OFF + buf * 8, par[buf]);
            par[buf] ^= 1;
            load_tile(kt + 3, buf);
        }
    }
    MBARRIER_WAIT_PARITY(smb + MB_OFF + 8, par[1]);
    TCGEN05_FENCE_AFTER();

    // epilogue: D = 128 lanes x 128 cols fp32.
    {
        const int sub = warp & 3;
        const int row = bm * 128 + sub * 32 + lane;
        const uint32_t taddr = tmem + ((uint32_t)sub << 21);
        #pragma unroll
        for (int chunk = 0; chunk < 2; ++chunk) {
            const int c0 = (warp >> 2) * 64 + chunk * 32;
            uint32_t regs[32];
            LDTM_X32(regs, taddr + c0);
            TCGEN05_WAIT_LD();
            float sb[32];
            #pragma unroll
            for (int j = 0; j < 32; ++j)
                asm volatile("ld.shared.f32 %0, [%1];" : "=f"(sb[j]) : "r"(smb + BIAS_OFF + (c0 + j) * 4));

            if (MODE == 0) {
                const int cg0 = bn * 128 + c0;
                const int three = cg0 >> 9, head = (cg0 >> 5) & 15;
                const float sc = (three == 0) ? qscale : 1.0f;
                const int b_idx = row >> 6, rw = row & 63;
                __half2* dst = (__half2*)(g_qkv +
                    ((((size_t)b_idx * HEADS + head) * 3 + three) * WIN + rw) * DH);
                #pragma unroll
                for (int j = 0; j < 16; ++j) {
                    float v0 = (__uint_as_float(regs[2 * j])     + sb[2 * j])     * sc;
                    float v1 = (__uint_as_float(regs[2 * j + 1]) + sb[2 * j + 1]) * sc;
                    dst[j] = __floats2half2_rn(v0, v1);
                }
            } else {
                float* dst = outf + (size_t)row * KDIM + bn * 128 + c0;
                #pragma unroll
                for (int j = 0; j < 8; ++j) {
                    float4 v;
                    v.x = __uint_as_float(regs[4 * j])     + sb[4 * j];
                    v.y = __uint_as_float(regs[4 * j + 1]) + sb[4 * j + 1];
                    v.z = __uint_as_float(regs[4 * j + 2]) + sb[4 * j + 2];
                    v.w = __uint_as_float(regs[4 * j + 3]) + sb[4 * j + 3];
                    *(float4*)(dst + 4 * j) = v;
                }
            }
        }
    }
    TCGEN05_FENCE_BEFORE();
    __syncthreads();
    if (tid == 0) {
        MBARRIER_INVAL(smb + MB_OFF + 0);
        MBARRIER_INVAL(smb + MB_OFF + 8);
        MBARRIER_INVAL(smb + MB_OFF + 16);
    }
    __syncthreads();
    if (warp == 0) TCGEN05_DEALLOC(tmem, 128);

#else
    // ================= legacy mma.sync path =================
    __half* sA = (__half*)smem_raw;               // [2][128*40]
    __half* sB = sA + 2 * 128 * 40;               // [2][128*40]
    const int wm = warp >> 2, wn = warp & 3;

    float acc[4][4][4];
    #pragma unroll
    for (int i = 0; i < 4; ++i)
        #pragma unroll
        for (int j = 0; j < 4; ++j)
            #pragma unroll
            for (int e = 0; e < 4; ++e) acc[i][j][e] = 0.f;

    auto load_tile = [&](int kt, int buf) {
        __half* dA = sA + buf * 128 * 40;
        __half* dB = sB + buf * 128 * 40;
        #pragma unroll
        for (int c = tid; c < 512; c += 256) {
            int row = c >> 2, cc = c & 3;
            cpasync16(smem_u32(dA + row * 40 + cc * 8), gA + (size_t)row * KDIM + kt * 32 + cc * 8);
            cpasync16(smem_u32(dB + row * 40 + cc * 8), gB + (size_t)row * KDIM + kt * 32 + cc * 8);
        }
        asm volatile("cp.async.commit_group;\n" ::: "memory");
    };

    load_tile(0, 0);
    for (int kt = 0; kt < 16; ++kt) {
        const int buf = kt & 1;
        if (kt + 1 < 16) {
            load_tile(kt + 1, buf ^ 1);
            asm volatile("cp.async.wait_group 1;\n" ::: "memory");
        } else {
            asm volatile("cp.async.wait_group 0;\n" ::: "memory");
        }
        __syncthreads();

        const __half* cA = sA + buf * 128 * 40;
        const __half* cB = sB + buf * 128 * 40;
        #pragma unroll
        for (int kk = 0; kk < 2; ++kk) {
            uint32_t af[4][4];
            #pragma unroll
            for (int mi = 0; mi < 4; ++mi) {
                int row = wm * 64 + mi * 16 + (lane & 15);
                int col = kk * 16 + ((lane >> 4) << 3);
                ldsm_x4(af[mi], &cA[row * 40 + col]);
            }
            uint32_t bf[2][4];
            #pragma unroll
            for (int nh = 0; nh < 2; ++nh) {
                int row = wn * 32 + nh * 16 + (lane & 7) + ((lane & 16) ? 8 : 0);
                int col = kk * 16 + ((lane & 8) ? 8 : 0);
                ldsm_x4(bf[nh], &cB[row * 40 + col]);
            }
            #pragma unroll
            for (int mi = 0; mi < 4; ++mi)
                #pragma unroll
                for (int ni = 0; ni < 4; ++ni)
                    mma16816(acc[mi][ni], af[mi], bf[ni >> 1][(ni & 1) * 2],
                             bf[ni >> 1][(ni & 1) * 2 + 1]);
        }
        __syncthreads();
    }

    const int g = lane >> 2, t = lane & 3;
    #pragma unroll
    for (int mi = 0; mi < 4; ++mi) {
        #pragma unroll
        for (int ni = 0; ni < 4; ++ni) {
            int col = bn * 128 + wn * 32 + ni * 8 + 2 * t;
            float bc0 = bias[col], bc1 = bias[col + 1];
            #pragma unroll
            for (int hh = 0; hh < 2; ++hh) {
                int row = bm * 128 + wm * 64 + mi * 16 + g + hh * 8;
                float v0 = acc[mi][ni][hh * 2 + 0] + bc0;
                float v1 = acc[mi][ni][hh * 2 + 1] + bc1;
                if (MODE == 0) {
                    int three = col >> 9, head = (col >> 5) & 15, d = col & 31;
                    if (three == 0) { v0 *= qscale; v1 *= qscale; }
                    size_t dst = ((((size_t)(row >> 6) * HEADS + head) * 3 + three) * WIN
                                  + (row & 63)) * DH + d;
                    *(__half2*)(g_qkv + dst) = __floats2half2_rn(v0, v1);
                } else {
                    *(float2*)(outf + (size_t)row * KDIM + col) = make_float2(v0, v1);
                }
            }
        }
    }
#endif
}

// ---------------- window attention: one CTA per (window, head) ----------------
__global__ __launch_bounds__(128) void attn_kernel(const float* __restrict__ table) {
    __shared__ __half sq[64 * 40], sk[64 * 40], sv[64 * 40];
    __shared__ float stab[225];

    const int bh = blockIdx.x;
    const int h = bh & (HEADS - 1);
    const int tid = threadIdx.x, lane = tid & 31, warp = tid >> 5;

    const __half* base = g_qkv + (size_t)bh * 3 * WIN * DH;
    for (int c = tid; c < 768; c += 128) {
        int mat = c >> 8, rc = c & 255, row = rc >> 2, cc = rc & 3;
        float4 v = *(const float4*)(base + mat * 2048 + row * 32 + cc * 8);
        __half* dst = (mat == 0) ? sq : (mat == 1) ? sk : sv;
        *(float4*)(dst + row * 40 + cc * 8) = v;
    }
    for (int i = tid; i < 225; i += 128) stab[i] = table[h * 225 + i];
    __syncthreads();

    const int r0 = warp * 16;
    float s[8][4];
    #pragma unroll
    for (int i = 0; i < 8; ++i)
        #pragma unroll
        for (int e = 0; e < 4; ++e) s[i][e] = 0.f;

    #pragma unroll
    for (int kk = 0; kk < 2; ++kk) {
        uint32_t a[4];
        {
            int row = r0 + (lane & 15);
            int col = kk * 16 + ((lane >> 4) << 3);
            ldsm_x4(a, &sq[row * 40 + col]);
        }
        #pragma unroll
        for (int nh = 0; nh < 4; ++nh) {
            uint32_t b[4];
            int row = nh * 16 + (lane & 7) + ((lane & 16) ? 8 : 0);
            int col = kk * 16 + ((lane & 8) ? 8 : 0);
            ldsm_x4(b, &sk[row * 40 + col]);
            mma16816(s[nh * 2],     a, b[0], b[1]);
            mma16816(s[nh * 2 + 1], a, b[2], b[3]);
        }
    }

    const int g = lane >> 2, t = lane & 3;
    const int i0 = r0 + g, i1 = r0 + 8 + g;
    const int ir0 = (i0 >> 3) + 7, ic0 = (i0 & 7) + 7;
    const int ir1 = (i1 >> 3) + 7, ic1 = (i1 & 7) + 7;

    float mx0 = -1e30f, mx1 = -1e30f;
    #pragma unroll
    for (int nt = 0; nt < 8; ++nt) {
        #pragma unroll
        for (int e = 0; e < 2; ++e) {
            int m = nt * 8 + 2 * t + e;
            int dr = m >> 3, dc = m & 7;
            s[nt][e]     += stab[(ir0 - dr) * 15 + (ic0 - dc)];
            s[nt][2 + e] += stab[(ir1 - dr) * 15 + (ic1 - dc)];
            mx0 = fmaxf(mx0, s[nt][e]);
            mx1 = fmaxf(mx1, s[nt][2 + e]);
        }
    }
    mx0 = fmaxf(mx0, __shfl_xor_sync(0xffffffffu, mx0, 1));
    mx0 = fmaxf(mx0, __shfl_xor_sync(0xffffffffu, mx0, 2));
    mx1 = fmaxf(mx1, __shfl_xor_sync(0xffffffffu, mx1, 1));
    mx1 = fmaxf(mx1, __shfl_xor_sync(0xffffffffu, mx1, 2));

    float sum0 = 0.f, sum1 = 0.f;
    #pragma unroll
    for (int nt = 0; nt < 8; ++nt) {
        #pragma unroll
        for (int e = 0; e < 2; ++e) {
            s[nt][e]     = __expf(s[nt][e] - mx0);     sum0 += s[nt][e];
            s[nt][2 + e] = __expf(s[nt][2 + e] - mx1); sum1 += s[nt][2 + e];
        }
    }
    sum0 += __shfl_xor_sync(0xffffffffu, sum0, 1);
    sum0 += __shfl_xor_sync(0xffffffffu, sum0, 2);
    sum1 += __shfl_xor_sync(0xffffffffu, sum1, 1);
    sum1 += __shfl_xor_sync(0xffffffffu, sum1, 2);
    const float inv0 = 1.f / sum0, inv1 = 1.f / sum1;
    #pragma unroll
    for (int nt = 0; nt < 8; ++nt) {
        s[nt][0] *= inv0; s[nt][1] *= inv0;
        s[nt][2] *= inv1; s[nt][3] *= inv1;
    }

    float o[4][4];
    #pragma unroll
    for (int i = 0; i < 4; ++i)
        #pragma unroll
        for (int e = 0; e < 4; ++e) o[i][e] = 0.f;

    #pragma unroll
    for (int kk = 0; kk < 4; ++kk) {
        uint32_t pa[4];
        pa[0] = packh2(s[2 * kk][0],     s[2 * kk][1]);
        pa[1] = packh2(s[2 * kk][2],     s[2 * kk][3]);
        pa[2] = packh2(s[2 * kk + 1][0], s[2 * kk + 1][1]);
        pa[3] = packh2(s[2 * kk + 1][2], s[2 * kk + 1][3]);
        #pragma unroll
        for (int nh = 0; nh < 2; ++nh) {
            uint32_t b[4];
            int row = kk * 16 + (lane & 7) + ((lane & 8) ? 8 : 0);
            int col = nh * 16 + ((lane & 16) ? 8 : 0);
            ldsm_x4_t(b, &sv[row * 40 + col]);
            mma16816(o[nh * 2],     pa, b[0], b[1]);
            mma16816(o[nh * 2 + 1], pa, b[2], b[3]);
        }
    }

    const int b_idx = bh >> 4;
    const size_t row0 = (size_t)b_idx * 64 + i0;
    const size_t row1 = (size_t)b_idx * 64 + i1;
    #pragma unroll
    for (int ni = 0; ni < 4; ++ni) {
        int col = h * 32 + ni * 8 + 2 * t;
        *(__half2*)(g_attnout + row0 * KDIM + col) = __floats2half2_rn(o[ni][0], o[ni][1]);
        *(__half2*)(g_attnout + row1 * KDIM + col) = __floats2half2_rn(o[ni][2], o[ni][3]);
    }
}

// ---------------- launch ----------------
extern "C" void kernel_launch(void* const* d_in, const int* in_sizes, int n_in,
                              void* d_out, int out_size) {
    const float* x     = (const float*)d_in[0];
    const float* wqkv  = (const float*)d_in[1];
    const float* bqkv  = (const float*)d_in[2];
    const float* tab   = (const float*)d_in[3];
    const float* wproj = (const float*)d_in[4];
    const float* bproj = (const float*)d_in[5];
    float* out = (float*)d_out;

    static int smem_set = 0;
    if (!smem_set) {
        cudaFuncSetAttribute(gemm_tc_kernel<0>, cudaFuncAttributeMaxDynamicSharedMemorySize, GEMM_SMEM_BYTES);
        cudaFuncSetAttribute(gemm_tc_kernel<1>, cudaFuncAttributeMaxDynamicSharedMemorySize, GEMM_SMEM_BYTES);
        smem_set = 1;
    }

    conv_x_kernel<<<65536, 256>>>(x);
    conv_w_kernel<<<3072, 256>>>(wqkv, wproj);
    gemm_tc_kernel<0><<<dim3(NQKV / 128, MTOT / 128), 256, GEMM_SMEM_BYTES>>>(bqkv, nullptr);
    attn_kernel<<<NB * HEADS, 128>>>(tab);
    gemm_tc_kernel<1><<<dim3(KDIM / 128, MTOT / 128), 256, GEMM_SMEM_BYTES>>>(bproj, out);
}

// round 14
// speedup vs baseline: 1.5063x; 1.0188x over previous
#include <cuda_runtime.h>
#include <cuda_fp16.h>
#include <stdint.h>

#define MTOT  131072
#define KDIM  512
#define NQKV  1536
#define HEADS 16
#define DH    32
#define WIN   64
#define NB    2048

// ---------------- scratch (device globals; allocation-free) ----------------
__device__ __half g_xh[(size_t)MTOT * KDIM];        // x in fp16           128MB
__device__ __half g_wqkv_t[(size_t)NQKV * KDIM];    // w_qkv^T fp16        1.5MB
__device__ __half g_wproj_t[(size_t)KDIM * KDIM];   // w_proj^T fp16       0.5MB
__device__ __half g_qkv[(size_t)NB * HEADS * 3 * WIN * DH];  // q,k,v      384MB
__device__ __half g_attnout[(size_t)MTOT * KDIM];   // attention output    128MB

// ---------------- PTX helpers (arch-portable) ----------------
__device__ __forceinline__ uint32_t smem_u32(const void* p) {
    uint32_t a;
    asm("{ .reg .u64 t; cvta.to.shared.u64 t, %1; cvt.u32.u64 %0, t; }" : "=r"(a) : "l"(p));
    return a;
}
__device__ __forceinline__ void cpasync16(uint32_t s, const void* g) {
    asm volatile("cp.async.cg.shared.global [%0], [%1], 16;\n" :: "r"(s), "l"(g));
}
__device__ __forceinline__ void ldsm_x4(uint32_t* r, const void* p) {
    uint32_t a = smem_u32(p);
    asm volatile("ldmatrix.sync.aligned.m8n8.x4.shared.b16 {%0,%1,%2,%3}, [%4];"
                 : "=r"(r[0]), "=r"(r[1]), "=r"(r[2]), "=r"(r[3]) : "r"(a));
}
__device__ __forceinline__ void ldsm_x4_t(uint32_t* r, const void* p) {
    uint32_t a = smem_u32(p);
    asm volatile("ldmatrix.sync.aligned.m8n8.x4.trans.shared.b16 {%0,%1,%2,%3}, [%4];"
                 : "=r"(r[0]), "=r"(r[1]), "=r"(r[2]), "=r"(r[3]) : "r"(a));
}
__device__ __forceinline__ void mma16816(float* c, const uint32_t* a, uint32_t b0, uint32_t b1) {
    asm volatile(
        "mma.sync.aligned.m16n8k16.row.col.f32.f16.f16.f32 "
        "{%0,%1,%2,%3},{%4,%5,%6,%7},{%8,%9},{%0,%1,%2,%3};"
        : "+f"(c[0]), "+f"(c[1]), "+f"(c[2]), "+f"(c[3])
        : "r"(a[0]), "r"(a[1]), "r"(a[2]), "r"(a[3]), "r"(b0), "r"(b1));
}
__device__ __forceinline__ uint32_t packh2(float a, float b) {
    __half2 h = __floats2half2_rn(a, b);
    return *(uint32_t*)&h;
}

#define HAS_TCGEN05 (defined(__CUDA_ARCH_FEAT_SM103_ALL) || defined(__CUDA_ARCH_FEAT_SM100_ALL) || defined(__CUDA_ARCH_FEAT_SM101_ALL))

#if HAS_TCGEN05
__device__ __forceinline__ uint32_t elect_one() {
    uint32_t p;
    asm volatile("{\n\t.reg .pred p;\n\telect.sync _|p, 0xFFFFFFFF;\n\tselp.b32 %0, 1, 0, p;\n\t}" : "=r"(p));
    return p;
}
// SW128 smem descriptor: layout=2 (SW128), version=1, SBO=64, LBO=1
#define SMEM_DESC_BASE \
    ((uint64_t(2) << 61) | (uint64_t(1) << 46) | (uint64_t(64) << 32) | (uint64_t(1) << 16))
#define MAKE_DESC(addr) (SMEM_DESC_BASE | (((uint64_t)((addr) >> 4)) & 0x3FFF))

#define MBARRIER_INIT(a, n) \
    asm volatile("mbarrier.init.shared.b64 [%0], %1;" :: "r"((uint32_t)(a)), "r"((uint32_t)(n)) : "memory")
#define MBARRIER_INVAL(a) \
    asm volatile("mbarrier.inval.shared.b64 [%0];" :: "r"((uint32_t)(a)) : "memory")
#define MBARRIER_WAIT_PARITY(mbar_smem_addr, phase_parity) do { \
    uint32_t _mbar = (uint32_t)(mbar_smem_addr); \
    uint32_t _parity = (uint32_t)(phase_parity); \
    uint32_t _done; \
    asm volatile( \
        "{\n\t.reg .pred p;\n\t" \
        "mbarrier.try_wait.parity.acquire.cta.shared::cta.b64 p, [%1], %2;\n\t" \
        "selp.b32 %0, 1, 0, p;\n\t}" \
        : "=r"(_done) : "r"(_mbar), "r"(_parity) : "memory"); \
    if (!_done) { \
        asm volatile( \
            "{\n\t.reg .pred P1;\n\t" \
            "WAIT_LOOP_%=:\n\t" \
            "mbarrier.try_wait.parity.acquire.cta.shared::cta.b64 P1, [%0], %1, 0x989680;\n\t" \
            "@P1 bra.uni WAIT_DONE_%=;\n\t" \
            "bra.uni WAIT_LOOP_%=;\n\t" \
            "WAIT_DONE_%=:\n\t}" \
            :: "r"(_mbar), "r"(_parity) : "memory"); \
    } \
} while(0)

#define TCGEN05_ALLOC(sa, n) \
    asm volatile("tcgen05.alloc.cta_group::1.sync.aligned.shared::cta.b32 [%0], %1;" \
                 :: "r"((uint32_t)(sa)), "r"((uint32_t)(n)) : "memory")
#define TCGEN05_DEALLOC(t, n) \
    asm volatile("tcgen05.dealloc.cta_group::1.sync.aligned.b32 %0, %1;" :: "r"(t), "r"((uint32_t)(n)))
#define TCGEN05_RELINQ() \
    asm volatile("tcgen05.relinquish_alloc_permit.cta_group::1.sync.aligned;")
#define TCGEN05_COMMIT(a) \
    asm volatile("tcgen05.commit.cta_group::1.mbarrier::arrive::one.shared::cluster.b64 [%0];" \
                 :: "r"((uint32_t)(a)) : "memory")
#define TCGEN05_WAIT_LD()  asm volatile("tcgen05.wait::ld.sync.aligned;" ::: "memory")
#define TCGEN05_FENCE_BEFORE() asm volatile("tcgen05.fence::before_thread_sync;" ::: "memory")
#define TCGEN05_FENCE_AFTER()  asm volatile("tcgen05.fence::after_thread_sync;" ::: "memory")
#define FENCE_PROXY_ASYNC() asm volatile("fence.proxy.async.shared::cta;" ::: "memory")

__device__ __forceinline__ void tc_mma_f16_ss(uint32_t d_tmem, uint64_t a_desc, uint64_t b_desc,
                                              uint32_t idesc, uint32_t en) {
    asm volatile(
        "{\n\t.reg .pred p;\n\tsetp.ne.u32 p, %4, 0;\n\t"
        "tcgen05.mma.cta_group::1.kind::f16 [%0], %1, %2, %3, {%5,%5,%5,%5}, p;\n\t}"
        :: "r"(d_tmem), "l"(a_desc), "l"(b_desc), "r"(idesc), "r"(en), "r"(0u)
        : "memory");
}

#define LDTM_X32(r, addr) \
    asm volatile( \
        "tcgen05.ld.sync.aligned.32x32b.x32.b32 " \
        "{%0, %1, %2, %3, %4, %5, %6, %7, " \
        " %8, %9, %10, %11, %12, %13, %14, %15, " \
        " %16, %17, %18, %19, %20, %21, %22, %23, " \
        " %24, %25, %26, %27, %28, %29, %30, %31}, [%32];" \
        : "=r"((r)[0]),  "=r"((r)[1]),  "=r"((r)[2]),  "=r"((r)[3]), \
          "=r"((r)[4]),  "=r"((r)[5]),  "=r"((r)[6]),  "=r"((r)[7]), \
          "=r"((r)[8]),  "=r"((r)[9]),  "=r"((r)[10]), "=r"((r)[11]), \
          "=r"((r)[12]), "=r"((r)[13]), "=r"((r)[14]), "=r"((r)[15]), \
          "=r"((r)[16]), "=r"((r)[17]), "=r"((r)[18]), "=r"((r)[19]), \
          "=r"((r)[20]), "=r"((r)[21]), "=r"((r)[22]), "=r"((r)[23]), \
          "=r"((r)[24]), "=r"((r)[25]), "=r"((r)[26]), "=r"((r)[27]), \
          "=r"((r)[28]), "=r"((r)[29]), "=r"((r)[30]), "=r"((r)[31]) \
        : "r"(addr))
#endif  // HAS_TCGEN05

// ---------------- converters ----------------
__global__ void conv_x_kernel(const float* __restrict__ x) {
    size_t i = (size_t)blockIdx.x * blockDim.x + threadIdx.x;
    float4 v = *(const float4*)(x + i * 4);
    __half2 a = __floats2half2_rn(v.x, v.y);
    __half2 b = __floats2half2_rn(v.z, v.w);
    uint2 o;
    o.x = *(uint32_t*)&a;
    o.y = *(uint32_t*)&b;
    *(uint2*)(g_xh + i * 4) = o;
}

__global__ void conv_w_kernel(const float* __restrict__ wqkv, const float* __restrict__ wproj) {
    int i = blockIdx.x * blockDim.x + threadIdx.x;
    if (i < NQKV * KDIM) {
        int n = i >> 9, k = i & 511;
        g_wqkv_t[i] = __float2half_rn(wqkv[(size_t)k * NQKV + n]);
    }
    if (i < KDIM * KDIM) {
        int n = i >> 9, k = i & 511;
        g_wproj_t[i] = __float2half_rn(wproj[(size_t)k * KDIM + n]);
    }
}

// ---------------- GEMM: C tile[128x128] = A[128x512] x Bt[128x512]^T ----------------
// grid: (Ntiles, Mtiles), blockIdx.x = bn (fastest -> L2 A-panel reuse), 256 threads.
// Two device paths: tcgen05 (sm_103a cubin) / legacy mma.sync (compute_103 PTX).
#define GEMM_SMEM_BYTES 99872   // max of both paths, incl. 1KB alignment slack

template <int MODE>   // 0 = qkv epilogue, 1 = proj epilogue
__global__ __launch_bounds__(256)
void gemm_tc_kernel(const float* __restrict__ bias, float* __restrict__ outf) {
    extern __shared__ char smem_raw[];
    const int bn = blockIdx.x, bm = blockIdx.y;
    const int tid = threadIdx.x, lane = tid & 31, warp = tid >> 5;

    const __half* A  = (MODE == 0) ? g_xh     : g_attnout;
    const __half* Bt = (MODE == 0) ? g_wqkv_t : g_wproj_t;
    const __half* gA = A  + (size_t)bm * 128 * KDIM;
    const __half* gB = Bt + (size_t)bn * 128 * KDIM;
    const float qscale = 0.17677669529663687f;   // 1/sqrt(32)

#if HAS_TCGEN05
    // ================= tcgen05 path =================
    const uint32_t smb = (smem_u32(smem_raw) + 1023u) & ~1023u;   // 1KB-align for SW128 desc
    const uint32_t BIAS_OFF = 98304, STM_OFF = 98816, MB_OFF = 98824;

    if (tid == 0) {
        MBARRIER_INIT(smb + MB_OFF + 0, 1);
        MBARRIER_INIT(smb + MB_OFF + 8, 1);
        MBARRIER_INIT(smb + MB_OFF + 16, 1);
    }
    if (warp == 0) {
        TCGEN05_ALLOC(smb + STM_OFF, 128);
        TCGEN05_RELINQ();
    }
    if (tid < 128) {
        float b = bias[bn * 128 + tid];
        asm volatile("st.shared.f32 [%0], %1;" :: "r"(smb + BIAS_OFF + tid * 4), "f"(b));
    }
    __syncthreads();
    uint32_t tmem;
    asm volatile("ld.shared.b32 %0, [%1];" : "=r"(tmem) : "r"(smb + STM_OFF));

    // stage buffer: A 16KB + B 16KB, 3 stages
    auto load_tile = [&](int t, int buf) {
        const __half* gAk = gA + t * 64;
        const __half* gBk = gB + t * 64;
        const uint32_t base = smb + buf * 32768;
        #pragma unroll
        for (int c = 0; c < 8; ++c) {
            int idx = tid + c * 256;                 // 0..2047
            int isB = idx >> 10;
            int e = idx & 1023;
            int row = e >> 3, c16 = e & 7;
            uint32_t off = row * 128 + c16 * 16;
            uint32_t sw = off ^ ((off >> 3) & 0x70);
            const __half* src = (isB ? gBk : gAk) + (size_t)row * KDIM + c16 * 8;
            cpasync16(base + isB * 16384 + sw, src);
        }
        asm volatile("cp.async.commit_group;\n" ::: "memory");
    };

    load_tile(0, 0);
    load_tile(1, 1);
    load_tile(2, 2);

    const uint32_t idesc = (1u << 4) | ((128u / 8) << 17) | ((128u / 16) << 24);
    int par[3] = {0, 0, 0};
    #pragma unroll
    for (int kt = 0; kt < 8; ++kt) {
        const int buf = kt % 3;
        const int pend = (7 - kt) > 2 ? 2 : (7 - kt);
        if (pend == 2)      asm volatile("cp.async.wait_group 2;\n" ::: "memory");
        else if (pend == 1) asm volatile("cp.async.wait_group 1;\n" ::: "memory");
        else                asm volatile("cp.async.wait_group 0;\n" ::: "memory");
        FENCE_PROXY_ASYNC();
        __syncthreads();

        if (warp == 0 && elect_one()) {
            uint64_t ad = MAKE_DESC(smb + buf * 32768);
            uint64_t bd = MAKE_DESC(smb + buf * 32768 + 16384);
            #pragma unroll
            for (int s = 0; s < 4; ++s)
                tc_mma_f16_ss(tmem, ad + s * 2, bd + s * 2, idesc, (kt > 0 || s > 0) ? 1u : 0u);
            TCGEN05_COMMIT(smb + MB_OFF + buf * 8);
        }

        if (kt + 3 < 8) {
            MBARRIER_WAIT_PARITY(smb + MB_OFF + buf * 8, par[buf]);
            par[buf] ^= 1;
            load_tile(kt + 3, buf);
        }
    }
    MBARRIER_WAIT_PARITY(smb + MB_OFF + 8, par[1]);
    TCGEN05_FENCE_AFTER();

    // epilogue: D = 128 lanes x 128 cols fp32.
    {
        const int sub = warp & 3;
        const int row = bm * 128 + sub * 32 + lane;
        const uint32_t taddr = tmem + ((uint32_t)sub << 21);
        #pragma unroll
        for (int chunk = 0; chunk < 2; ++chunk) {
            const int c0 = (warp >> 2) * 64 + chunk * 32;
            uint32_t regs[32];
            LDTM_X32(regs, taddr + c0);
            TCGEN05_WAIT_LD();
            float sb[32];
            #pragma unroll
            for (int j = 0; j < 32; ++j)
                asm volatile("ld.shared.f32 %0, [%1];" : "=f"(sb[j]) : "r"(smb + BIAS_OFF + (c0 + j) * 4));

            if (MODE == 0) {
                const int cg0 = bn * 128 + c0;
                const int three = cg0 >> 9, head = (cg0 >> 5) & 15;
                const float sc = (three == 0) ? qscale : 1.0f;
                const int b_idx = row >> 6, rw = row & 63;
                __half2* dst = (__half2*)(g_qkv +
                    ((((size_t)b_idx * HEADS + head) * 3 + three) * WIN + rw) * DH);
                #pragma unroll
                for (int j = 0; j < 16; ++j) {
                    float v0 = (__uint_as_float(regs[2 * j])     + sb[2 * j])     * sc;
                    float v1 = (__uint_as_float(regs[2 * j + 1]) + sb[2 * j + 1]) * sc;
                    dst[j] = __floats2half2_rn(v0, v1);
                }
            } else {
                float* dst = outf + (size_t)row * KDIM + bn * 128 + c0;
                #pragma unroll
                for (int j = 0; j < 8; ++j) {
                    float4 v;
                    v.x = __uint_as_float(regs[4 * j])     + sb[4 * j];
                    v.y = __uint_as_float(regs[4 * j + 1]) + sb[4 * j + 1];
                    v.z = __uint_as_float(regs[4 * j + 2]) + sb[4 * j + 2];
                    v.w = __uint_as_float(regs[4 * j + 3]) + sb[4 * j + 3];
                    *(float4*)(dst + 4 * j) = v;
                }
            }
        }
    }
    TCGEN05_FENCE_BEFORE();
    __syncthreads();
    if (tid == 0) {
        MBARRIER_INVAL(smb + MB_OFF + 0);
        MBARRIER_INVAL(smb + MB_OFF + 8);
        MBARRIER_INVAL(smb + MB_OFF + 16);
    }
    __syncthreads();
    if (warp == 0) TCGEN05_DEALLOC(tmem, 128);

#else
    // ================= legacy mma.sync path =================
    __half* sA = (__half*)smem_raw;               // [2][128*40]
    __half* sB = sA + 2 * 128 * 40;               // [2][128*40]
    const int wm = warp >> 2, wn = warp & 3;

    float acc[4][4][4];
    #pragma unroll
    for (int i = 0; i < 4; ++i)
        #pragma unroll
        for (int j = 0; j < 4; ++j)
            #pragma unroll
            for (int e = 0; e < 4; ++e) acc[i][j][e] = 0.f;

    auto load_tile = [&](int kt, int buf) {
        __half* dA = sA + buf * 128 * 40;
        __half* dB = sB + buf * 128 * 40;
        #pragma unroll
        for (int c = tid; c < 512; c += 256) {
            int row = c >> 2, cc = c & 3;
            cpasync16(smem_u32(dA + row * 40 + cc * 8), gA + (size_t)row * KDIM + kt * 32 + cc * 8);
            cpasync16(smem_u32(dB + row * 40 + cc * 8), gB + (size_t)row * KDIM + kt * 32 + cc * 8);
        }
        asm volatile("cp.async.commit_group;\n" ::: "memory");
    };

    load_tile(0, 0);
    for (int kt = 0; kt < 16; ++kt) {
        const int buf = kt & 1;
        if (kt + 1 < 16) {
            load_tile(kt + 1, buf ^ 1);
            asm volatile("cp.async.wait_group 1;\n" ::: "memory");
        } else {
            asm volatile("cp.async.wait_group 0;\n" ::: "memory");
        }
        __syncthreads();

        const __half* cA = sA + buf * 128 * 40;
        const __half* cB = sB + buf * 128 * 40;
        #pragma unroll
        for (int kk = 0; kk < 2; ++kk) {
            uint32_t af[4][4];
            #pragma unroll
            for (int mi = 0; mi < 4; ++mi) {
                int row = wm * 64 + mi * 16 + (lane & 15);
                int col = kk * 16 + ((lane >> 4) << 3);
                ldsm_x4(af[mi], &cA[row * 40 + col]);
            }
            uint32_t bf[2][4];
            #pragma unroll
            for (int nh = 0; nh < 2; ++nh) {
                int row = wn * 32 + nh * 16 + (lane & 7) + ((lane & 16) ? 8 : 0);
                int col = kk * 16 + ((lane & 8) ? 8 : 0);
                ldsm_x4(bf[nh], &cB[row * 40 + col]);
            }
            #pragma unroll
            for (int mi = 0; mi < 4; ++mi)
                #pragma unroll
                for (int ni = 0; ni < 4; ++ni)
                    mma16816(acc[mi][ni], af[mi], bf[ni >> 1][(ni & 1) * 2],
                             bf[ni >> 1][(ni & 1) * 2 + 1]);
        }
        __syncthreads();
    }

    const int g = lane >> 2, t = lane & 3;
    #pragma unroll
    for (int mi = 0; mi < 4; ++mi) {
        #pragma unroll
        for (int ni = 0; ni < 4; ++ni) {
            int col = bn * 128 + wn * 32 + ni * 8 + 2 * t;
            float bc0 = bias[col], bc1 = bias[col + 1];
            #pragma unroll
            for (int hh = 0; hh < 2; ++hh) {
                int row = bm * 128 + wm * 64 + mi * 16 + g + hh * 8;
                float v0 = acc[mi][ni][hh * 2 + 0] + bc0;
                float v1 = acc[mi][ni][hh * 2 + 1] + bc1;
                if (MODE == 0) {
                    int three = col >> 9, head = (col >> 5) & 15, d = col & 31;
                    if (three == 0) { v0 *= qscale; v1 *= qscale; }
                    size_t dst = ((((size_t)(row >> 6) * HEADS + head) * 3 + three) * WIN
                                  + (row & 63)) * DH + d;
                    *(__half2*)(g_qkv + dst) = __floats2half2_rn(v0, v1);
                } else {
                    *(float2*)(outf + (size_t)row * KDIM + col) = make_float2(v0, v1);
                }
            }
        }
    }
#endif
}

// ---------------- window attention: one CTA per TWO (window, head) pairs ----------------
// 256 threads; warps 0-3 -> pair 0, warps 4-7 -> pair 1. Per-warp math identical to R2.
// Output staged in smem (dead sq region) then written as coalesced 16B float4s.
__global__ __launch_bounds__(256) void attn_kernel(const float* __restrict__ table) {
    __shared__ __half sqkv[2][3][64 * 40];
    __shared__ float stab2[2][225];

    const int pair0 = blockIdx.x * 2;
    const int tid = threadIdx.x, lane = tid & 31, warp = tid >> 5;

    // load qkv for both pairs: 1536 x 16B chunks
    const __half* base = g_qkv + (size_t)blockIdx.x * 2 * 3 * WIN * DH;
    #pragma unroll
    for (int it = 0; it < 6; ++it) {
        int c = tid + it * 256;                  // 0..1535
        int p = c / 768;
        int r = c - p * 768;
        int mat = r >> 8, rc = r & 255, row = rc >> 2, cc = rc & 3;
        float4 v = *(const float4*)(base + p * 6144 + mat * 2048 + row * 32 + cc * 8);
        *(float4*)(&sqkv[p][mat][row * 40 + cc * 8]) = v;
    }
    for (int i = tid; i < 450; i += 256) {
        int pp = i / 225, j = i - pp * 225;
        stab2[pp][j] = table[((pair0 + pp) & (HEADS - 1)) * 225 + j];
    }
    __syncthreads();

    const int pair = warp >> 2, ww = warp & 3;
    const __half* sq = sqkv[pair][0];
    const __half* sk = sqkv[pair][1];
    const __half* sv = sqkv[pair][2];
    const float* stab = stab2[pair];

    const int r0 = ww * 16;
    float s[8][4];
    #pragma unroll
    for (int i = 0; i < 8; ++i)
        #pragma unroll
        for (int e = 0; e < 4; ++e) s[i][e] = 0.f;

    // S = q k^T (q pre-scaled)
    #pragma unroll
    for (int kk = 0; kk < 2; ++kk) {
        uint32_t a[4];
        {
            int row = r0 + (lane & 15);
            int col = kk * 16 + ((lane >> 4) << 3);
            ldsm_x4(a, &sq[row * 40 + col]);
        }
        #pragma unroll
        for (int nh = 0; nh < 4; ++nh) {
            uint32_t b[4];
            int row = nh * 16 + (lane & 7) + ((lane & 16) ? 8 : 0);
            int col = kk * 16 + ((lane & 8) ? 8 : 0);
            ldsm_x4(b, &sk[row * 40 + col]);
            mma16816(s[nh * 2],     a, b[0], b[1]);
            mma16816(s[nh * 2 + 1], a, b[2], b[3]);
        }
    }

    const int g = lane >> 2, t = lane & 3;
    const int i0 = r0 + g, i1 = r0 + 8 + g;
    const int ir0 = (i0 >> 3) + 7, ic0 = (i0 & 7) + 7;
    const int ir1 = (i1 >> 3) + 7, ic1 = (i1 & 7) + 7;

    float mx0 = -1e30f, mx1 = -1e30f;
    #pragma unroll
    for (int nt = 0; nt < 8; ++nt) {
        #pragma unroll
        for (int e = 0; e < 2; ++e) {
            int m = nt * 8 + 2 * t + e;
            int dr = m >> 3, dc = m & 7;
            s[nt][e]     += stab[(ir0 - dr) * 15 + (ic0 - dc)];
            s[nt][2 + e] += stab[(ir1 - dr) * 15 + (ic1 - dc)];
            mx0 = fmaxf(mx0, s[nt][e]);
            mx1 = fmaxf(mx1, s[nt][2 + e]);
        }
    }
    mx0 = fmaxf(mx0, __shfl_xor_sync(0xffffffffu, mx0, 1));
    mx0 = fmaxf(mx0, __shfl_xor_sync(0xffffffffu, mx0, 2));
    mx1 = fmaxf(mx1, __shfl_xor_sync(0xffffffffu, mx1, 1));
    mx1 = fmaxf(mx1, __shfl_xor_sync(0xffffffffu, mx1, 2));

    float sum0 = 0.f, sum1 = 0.f;
    #pragma unroll
    for (int nt = 0; nt < 8; ++nt) {
        #pragma unroll
        for (int e = 0; e < 2; ++e) {
            s[nt][e]     = __expf(s[nt][e] - mx0);     sum0 += s[nt][e];
            s[nt][2 + e] = __expf(s[nt][2 + e] - mx1); sum1 += s[nt][2 + e];
        }
    }
    sum0 += __shfl_xor_sync(0xffffffffu, sum0, 1);
    sum0 += __shfl_xor_sync(0xffffffffu, sum0, 2);
    sum1 += __shfl_xor_sync(0xffffffffu, sum1, 1);
    sum1 += __shfl_xor_sync(0xffffffffu, sum1, 2);
    const float inv0 = 1.f / sum0, inv1 = 1.f / sum1;
    #pragma unroll
    for (int nt = 0; nt < 8; ++nt) {
        s[nt][0] *= inv0; s[nt][1] *= inv0;
        s[nt][2] *= inv1; s[nt][3] *= inv1;
    }

    // O = P v
    float o[4][4];
    #pragma unroll
    for (int i = 0; i < 4; ++i)
        #pragma unroll
        for (int e = 0; e < 4; ++e) o[i][e] = 0.f;

    #pragma unroll
    for (int kk = 0; kk < 4; ++kk) {
        uint32_t pa[4];
        pa[0] = packh2(s[2 * kk][0],     s[2 * kk][1]);
        pa[1] = packh2(s[2 * kk][2],     s[2 * kk][3]);
        pa[2] = packh2(s[2 * kk + 1][0], s[2 * kk + 1][1]);
        pa[3] = packh2(s[2 * kk + 1][2], s[2 * kk + 1][3]);
        #pragma unroll
        for (int nh = 0; nh < 2; ++nh) {
            uint32_t b[4];
            int row = kk * 16 + (lane & 7) + ((lane & 8) ? 8 : 0);
            int col = nh * 16 + ((lane & 16) ? 8 : 0);
            ldsm_x4_t(b, &sv[row * 40 + col]);
            mma16816(o[nh * 2],     pa, b[0], b[1]);
            mma16816(o[nh * 2 + 1], pa, b[2], b[3]);
        }
    }

    // stage O into the (now dead) sq region, stride 32, then coalesced write-out
    __syncthreads();
    {
        __half* so = sqkv[pair][0];
        #pragma unroll
        for (int ni = 0; ni < 4; ++ni) {
            int col = ni * 8 + 2 * t;
            *(__half2*)(so + i0 * 32 + col) = __floats2half2_rn(o[ni][0], o[ni][1]);
            *(__half2*)(so + i1 * 32 + col) = __floats2half2_rn(o[ni][2], o[ni][3]);
        }
    }
    __syncthreads();

    // copy out: 512 assignments (2 pairs x 64 rows x 4 segs of 16B)
    #pragma unroll
    for (int it = 0; it < 2; ++it) {
        int j = tid + it * 256;                  // 0..511
        int p = j >> 8, rem = j & 255;
        int r = rem >> 2, seg = rem & 3;
        int bh = pair0 + p;
        int b = bh >> 4, h = bh & (HEADS - 1);
        float4 v = *(const float4*)(&sqkv[p][0][r * 32 + seg * 8]);
        *(float4*)(g_attnout + ((size_t)b * 64 + r) * KDIM + h * 32 + seg * 8) = v;
    }
}

// ---------------- launch ----------------
extern "C" void kernel_launch(void* const* d_in, const int* in_sizes, int n_in,
                              void* d_out, int out_size) {
    const float* x     = (const float*)d_in[0];
    const float* wqkv  = (const float*)d_in[1];
    const float* bqkv  = (const float*)d_in[2];
    const float* tab   = (const float*)d_in[3];
    const float* wproj = (const float*)d_in[4];
    const float* bproj = (const float*)d_in[5];
    float* out = (float*)d_out;

    static int smem_set = 0;
    if (!smem_set) {
        cudaFuncSetAttribute(gemm_tc_kernel<0>, cudaFuncAttributeMaxDynamicSharedMemorySize, GEMM_SMEM_BYTES);
        cudaFuncSetAttribute(gemm_tc_kernel<1>, cudaFuncAttributeMaxDynamicSharedMemorySize, GEMM_SMEM_BYTES);
        smem_set = 1;
    }

    conv_x_kernel<<<65536, 256>>>(x);
    conv_w_kernel<<<3072, 256>>>(wqkv, wproj);
    gemm_tc_kernel<0><<<dim3(NQKV / 128, MTOT / 128), 256, GEMM_SMEM_BYTES>>>(bqkv, nullptr);
    attn_kernel<<<NB * HEADS / 2, 256>>>(tab);
    gemm_tc_kernel<1><<<dim3(KDIM / 128, MTOT / 128), 256, GEMM_SMEM_BYTES>>>(bproj, out);
}